// round 2
// baseline (speedup 1.0000x reference)
#include <cuda_runtime.h>
#include <cstdint>
#include <math.h>

#define BB 64
#define SS 512
#define EE 256
#define HH 512
#define GG 2048
#define NBLK 128
#define BSH (BB*SS*HH)
#define KT 128
#define SCAN_SMEM 107008

__device__ float g_uproj[BB*SS*GG];
__device__ float g_h[2][BB*HH];
__device__ float g_c[2][BB*HH];
__device__ unsigned int g_ctr;

// ---------------- init: zero h0/c0 and barrier counter ----------------
__global__ void init_state() {
    int i = blockIdx.x * 256 + threadIdx.x;   // 128 blocks * 256 = 32768
    g_h[0][i] = 0.f;
    g_c[0][i] = 0.f;
    if (i == 0) g_ctr = 0u;
}

// ---------------- u_proj GEMM: [32768,256] x [2048,256]^T ----------------
__global__ void __launch_bounds__(256) gemm_uproj(
    const float* __restrict__ A,
    const float* __restrict__ W,
    const float* __restrict__ bias)
{
    __shared__ float As[8][132];
    __shared__ float Bs[8][132];

    const int tid  = threadIdx.x;
    const int bm   = blockIdx.y * 128;
    const int bn   = blockIdx.x * 128;
    const int tx   = tid & 15;
    const int ty   = tid >> 4;
    const int lrow = tid >> 1;
    const int lk   = (tid & 1) * 4;

    const float* Aptr = A + (size_t)(bm + lrow) * EE + lk;
    const float* Wptr = W + (size_t)(bn + lrow) * EE + lk;

    float acc[8][8];
#pragma unroll
    for (int r = 0; r < 8; r++)
#pragma unroll
        for (int c = 0; c < 8; c++) acc[r][c] = 0.f;

    float4 av = *(const float4*)(Aptr);
    float4 bv = *(const float4*)(Wptr);

    for (int k0 = 0; k0 < EE; k0 += 8) {
        __syncthreads();
        As[lk+0][lrow] = av.x; As[lk+1][lrow] = av.y;
        As[lk+2][lrow] = av.z; As[lk+3][lrow] = av.w;
        Bs[lk+0][lrow] = bv.x; Bs[lk+1][lrow] = bv.y;
        Bs[lk+2][lrow] = bv.z; Bs[lk+3][lrow] = bv.w;
        __syncthreads();
        if (k0 + 8 < EE) {
            av = *(const float4*)(Aptr + k0 + 8);
            bv = *(const float4*)(Wptr + k0 + 8);
        }
#pragma unroll
        for (int kk = 0; kk < 8; kk++) {
            float4 a0 = *(const float4*)&As[kk][ty*8];
            float4 a1 = *(const float4*)&As[kk][ty*8+4];
            float4 b0 = *(const float4*)&Bs[kk][tx*8];
            float4 b1 = *(const float4*)&Bs[kk][tx*8+4];
            float ar[8] = {a0.x,a0.y,a0.z,a0.w,a1.x,a1.y,a1.z,a1.w};
            float br[8] = {b0.x,b0.y,b0.z,b0.w,b1.x,b1.y,b1.z,b1.w};
#pragma unroll
            for (int r = 0; r < 8; r++)
#pragma unroll
                for (int c = 0; c < 8; c++) acc[r][c] += ar[r]*br[c];
        }
    }

    float bsr[8];
#pragma unroll
    for (int c = 0; c < 8; c++) bsr[c] = bias[bn + tx*8 + c];

#pragma unroll
    for (int r = 0; r < 8; r++) {
        float* cp = g_uproj + (size_t)(bm + ty*8 + r) * GG + bn + tx*8;
        float4 o0 = {acc[r][0]+bsr[0], acc[r][1]+bsr[1], acc[r][2]+bsr[2], acc[r][3]+bsr[3]};
        float4 o1 = {acc[r][4]+bsr[4], acc[r][5]+bsr[5], acc[r][6]+bsr[6], acc[r][7]+bsr[7]};
        *(float4*)(cp)     = o0;
        *(float4*)(cp + 4) = o1;
    }
}

// ---------------- persistent 512-step scan ----------------
__device__ __forceinline__ float sigf(float x) { return 1.0f / (1.0f + expf(-x)); }

__global__ void __launch_bounds__(256, 1) lstm_scan(
    const float* __restrict__ ts,
    const float* __restrict__ Wall,
    const float* __restrict__ ball,
    const float* __restrict__ Wd,
    const float* __restrict__ bd,
    float* __restrict__ out)
{
    extern __shared__ float sm[];
    float* sw  = sm;                  // [4 q][4 gate][512]
    float* swd = sm + 8192;           // [4 q][512]
    float* shh = sm + 10240;          // [64][129]
    float* shc = shh + 8256;          // [64][129]

    const int tid   = threadIdx.x;
    const int q     = tid >> 6;
    const int b     = tid & 63;
    const int jbase = blockIdx.x * 4;
    const int j     = jbase + q;

    for (int idx = tid; idx < 4*4*512; idx += 256) {
        int r = idx >> 9;
        int k = idx & 511;
        int qq = r >> 2, g = r & 3;
        sw[idx] = Wall[(size_t)(g*512 + jbase + qq) * 512 + k];
    }
    for (int idx = tid; idx < 4*512; idx += 256) {
        int qq = idx >> 9, k = idx & 511;
        swd[idx] = Wd[(size_t)(jbase + qq) * 512 + k];
    }
    const float bfb = ball[j];
    const float bib = ball[512 + j];
    const float bob = ball[1024 + j];
    const float bcb = ball[1536 + j];
    const float bdj = bd[j];
    __syncthreads();

    const int sb = tid >> 2;
    const int s2 = tid & 3;

    const float* wrow  = sw  + q * 4 * 512;
    const float* wdrow = swd + q * 512;

    float4 hreg[8], creg[8];

    for (int s = 0; s < SS; s++) {
        const float* hsrc = g_h[s & 1];
        const float* csrc = g_c[s & 1];

        const float* up = g_uproj + ((size_t)b * SS + s) * GG;
        float u0 = __ldg(up + j);
        float u1 = __ldg(up + 512 + j);
        float u2 = __ldg(up + 1024 + j);
        float u3 = __ldg(up + 1536 + j);
        float tv = __ldg(ts + b * SS + s);

        {   // prefetch tile 0 (L2-coherent loads)
            const float* hb = hsrc + sb * HH;
            const float* cb = csrc + sb * HH;
#pragma unroll
            for (int i = 0; i < 4; i++) {
                int k = s2 * 8 + 32 * i;
                hreg[i*2]   = __ldcg((const float4*)(hb + k));
                hreg[i*2+1] = __ldcg((const float4*)(hb + k + 4));
                creg[i*2]   = __ldcg((const float4*)(cb + k));
                creg[i*2+1] = __ldcg((const float4*)(cb + k + 4));
            }
        }

        float accf = 0.f, acci = 0.f, acco = 0.f, accc = 0.f, accd = 0.f;
        float c_old = 0.f;

        for (int t = 0; t < HH / KT; t++) {
            __syncthreads();
            {   // stage tile into pad-129 rows (conflict-free STS)
                float* hd = shh + sb * 129;
                float* cd = shc + sb * 129;
#pragma unroll
                for (int i = 0; i < 4; i++) {
                    int k = s2 * 8 + 32 * i;
                    float4 v0 = hreg[i*2], v1 = hreg[i*2+1];
                    hd[k+0]=v0.x; hd[k+1]=v0.y; hd[k+2]=v0.z; hd[k+3]=v0.w;
                    hd[k+4]=v1.x; hd[k+5]=v1.y; hd[k+6]=v1.z; hd[k+7]=v1.w;
                    float4 w0 = creg[i*2], w1 = creg[i*2+1];
                    cd[k+0]=w0.x; cd[k+1]=w0.y; cd[k+2]=w0.z; cd[k+3]=w0.w;
                    cd[k+4]=w1.x; cd[k+5]=w1.y; cd[k+6]=w1.z; cd[k+7]=w1.w;
                }
            }
            __syncthreads();
            if (t + 1 < HH / KT) {   // prefetch next tile
                const float* hb = hsrc + sb * HH + (t + 1) * KT;
                const float* cb = csrc + sb * HH + (t + 1) * KT;
#pragma unroll
                for (int i = 0; i < 4; i++) {
                    int k = s2 * 8 + 32 * i;
                    hreg[i*2]   = __ldcg((const float4*)(hb + k));
                    hreg[i*2+1] = __ldcg((const float4*)(hb + k + 4));
                    creg[i*2]   = __ldcg((const float4*)(cb + k));
                    creg[i*2+1] = __ldcg((const float4*)(cb + k + 4));
                }
            }
            const int kg0 = t * KT;
            const float* hp = shh + b * 129;
            const float* cp = shc + b * 129;
#pragma unroll 8
            for (int k = 0; k < KT; k += 4) {
                int kg = kg0 + k;
                float4 wf = *(const float4*)(wrow + kg);
                float4 wi = *(const float4*)(wrow + 512 + kg);
                float4 wo = *(const float4*)(wrow + 1024 + kg);
                float4 wc = *(const float4*)(wrow + 1536 + kg);
                float4 wd = *(const float4*)(wdrow + kg);
                float h0 = hp[k], h1 = hp[k+1], h2 = hp[k+2], h3 = hp[k+3];
                float c0 = cp[k], c1 = cp[k+1], c2 = cp[k+2], c3 = cp[k+3];
                accf += wf.x*h0; accf += wf.y*h1; accf += wf.z*h2; accf += wf.w*h3;
                acci += wi.x*h0; acci += wi.y*h1; acci += wi.z*h2; acci += wi.w*h3;
                acco += wo.x*h0; acco += wo.y*h1; acco += wo.z*h2; acco += wo.w*h3;
                accc += wc.x*h0; accc += wc.y*h1; accc += wc.z*h2; accc += wc.w*h3;
                accd += wd.x*c0; accd += wd.y*c1; accd += wd.z*c2; accd += wd.w*c3;
            }
            if ((j >> 7) == t) c_old = shc[b * 129 + (j & (KT - 1))];
        }

        float dec  = 1.0f / logf(2.718281828459045f + tv);
        float cs1  = tanhf(accd + bdj);
        float cadj = (c_old - cs1) + cs1 * dec;
        float f  = sigf(accf + bfb + u0);
        float ii = sigf(acci + bib + u1);
        float o  = sigf(acco + bob + u2);
        float ct = tanhf(accc + bcb + u3);
        float cn = f * cadj + ii * ct;
        float hn = o * tanhf(cn);

        const int nb = (s + 1) & 1;
        g_h[nb][b * HH + j] = hn;
        g_c[nb][b * HH + j] = cn;
        out[((size_t)b * SS + s) * HH + j] = hn;
        if (s == SS - 1) {
            out[BSH + b * HH + j]         = hn;
            out[BSH + BB*HH + b * HH + j] = cn;
        }

        if (s < SS - 1) {   // grid barrier
            __threadfence();
            __syncthreads();
            if (tid == 0) {
                atomicAdd(&g_ctr, 1u);
                unsigned target = (unsigned)(s + 1) * gridDim.x;
                volatile unsigned* p = &g_ctr;
                while (*p < target) { }
            }
            __syncthreads();
            __threadfence();
        }
    }
}

extern "C" void kernel_launch(void* const* d_in, const int* in_sizes, int n_in,
                              void* d_out, int out_size) {
    const float* inputs = (const float*)d_in[0];
    const float* tstamp = (const float*)d_in[1];
    const float* Wall   = (const float*)d_in[2];
    const float* ball   = (const float*)d_in[3];
    const float* Uall   = (const float*)d_in[4];
    const float* uball  = (const float*)d_in[5];
    const float* Wd     = (const float*)d_in[6];
    const float* bd     = (const float*)d_in[7];
    float* out = (float*)d_out;

    cudaFuncSetAttribute(lstm_scan, cudaFuncAttributeMaxDynamicSharedMemorySize, SCAN_SMEM);

    init_state<<<128, 256>>>();
    dim3 g1(GG / 128, (BB * SS) / 128);
    gemm_uproj<<<g1, 256>>>(inputs, Uall, uball);
    lstm_scan<<<NBLK, 256, SCAN_SMEM>>>(tstamp, Wall, ball, Wd, bd, out);
}